// round 4
// baseline (speedup 1.0000x reference)
#include <cuda_runtime.h>
#include <cuda_fp16.h>

#define N_NODES_C 50000
#define D_FEAT 64
#define D_OUT 64
#define N_REL 8
#define N_BASES 4
#define K_DIM 256
#define NODE_TILE 64
#define KC 64           /* k per chunk = 16 i * 4 b */
#define NCHUNK 4
#define TBLOCK 256

typedef unsigned long long ull;

// Scratch: transformed node features y[n][o] in fp16 (6.4 MB)
__device__ __half g_y[(size_t)N_NODES_C * D_OUT];

#define FMA2(acc, a, b) \
    asm("fma.rn.f32x2 %0, %1, %2, %0;" : "+l"(acc) : "l"(a), "l"(b))

__device__ __forceinline__ ull pack2(float v) {
    ull r; unsigned u = __float_as_uint(v);
    asm("mov.b64 %0, {%1, %1};" : "=l"(r) : "r"(u));
    return r;
}
__device__ __forceinline__ ull pack2pair(float lo, float hi) {
    ull r;
    asm("mov.b64 %0, {%1, %2};" : "=l"(r)
        : "r"(__float_as_uint(lo)), "r"(__float_as_uint(hi)));
    return r;
}
__device__ __forceinline__ float2 unpack2(ull v) {
    unsigned lo, hi;
    asm("mov.b64 {%0, %1}, %2;" : "=r"(lo), "=r"(hi) : "l"(v));
    return make_float2(__uint_as_float(lo), __uint_as_float(hi));
}

// ---------------------------------------------------------------------------
// Fused transform: y = (x @_r w_rel) @_{i,b} w_bases
// smem: wb_h [256 k][32 o-pairs] fp16 half2 (32KB),
//       z_s  [2 buf][64 k][64 n] fp32, xor-swizzled 16B groups (32KB),
//       wrel2_s [8 r][2 b-pair] f32x2
// One barrier per k-chunk (double-buffered z ring).
// ---------------------------------------------------------------------------
extern "C" __global__ void __launch_bounds__(TBLOCK, 3)
rgcn_transform(const float* __restrict__ x,
               const float* __restrict__ w_bases,
               const float* __restrict__ w_rel,
               int n_nodes, int n_tiles)
{
    extern __shared__ float smem[];
    __half2* wb_h  = (__half2*)smem;                       // 256*32 half2
    float*   z_s   = smem + (K_DIM * 32) / 1;              // after 32KB = 8192 floats
    ull*     wrel2_s = (ull*)(z_s + 2 * KC * NODE_TILE);   // 16 ulls

    const int t = threadIdx.x;

    if (t < N_REL * 2) {
        int r = t >> 1, bp = t & 1;
        wrel2_s[r * 2 + bp] = pack2pair(w_rel[r * 4 + 2 * bp],
                                        w_rel[r * 4 + 2 * bp + 1]);
    }
    // wb_h[k*32 + op] = half2(w[k][2op], w[k][2op+1]), k=(i*4+b)
    for (int idx = t; idx < K_DIM * 32; idx += TBLOCK) {
        int k = idx >> 5, op = idx & 31;
        int b = k & 3,   i = k >> 2;
        const float* src = w_bases + (b * D_FEAT + i) * D_OUT + op * 2;
        wb_h[idx] = __floats2half2_rn(src[0], src[1]);
    }
    __syncthreads();

    const int og = t >> 4;   // 16 out groups of 4 outs
    const int ng = t & 15;   // 16 node groups of 4 nodes
    const int ii = t & 15;   // Phase A: i within chunk (256 % 16 == 0)

    for (int tile = blockIdx.x; tile < n_tiles; tile += gridDim.x) {
        const int node0 = tile * NODE_TILE;

        ull acc[4][2];   // [node j][out-pair], f32x2 over outs
        #pragma unroll
        for (int j = 0; j < 4; j++) { acc[j][0] = 0ull; acc[j][1] = 0ull; }

        #pragma unroll
        for (int c = 0; c < NCHUNK; c++) {
            float* zb_buf = z_s + (c & 1) * (KC * NODE_TILE);

            // ---- Phase A: z chunk ---------------------------------------
            #pragma unroll
            for (int it = 0; it < (NODE_TILE * 16) / TBLOCK; it++) {  // 4
                int n = (t >> 4) + it * 16;       // node within tile
                int node = node0 + n;
                ull zp0 = 0ull, zp1 = 0ull;       // b-pairs (0,1),(2,3)
                if (node < n_nodes) {
                    const float4* xr = (const float4*)
                        (x + ((size_t)node * D_FEAT + (c * 16 + ii)) * N_REL);
                    float4 x0 = xr[0];
                    float4 x1 = xr[1];
                    ull xp;
                    xp = pack2(x0.x); FMA2(zp0, xp, wrel2_s[0]);  FMA2(zp1, xp, wrel2_s[1]);
                    xp = pack2(x0.y); FMA2(zp0, xp, wrel2_s[2]);  FMA2(zp1, xp, wrel2_s[3]);
                    xp = pack2(x0.z); FMA2(zp0, xp, wrel2_s[4]);  FMA2(zp1, xp, wrel2_s[5]);
                    xp = pack2(x0.w); FMA2(zp0, xp, wrel2_s[6]);  FMA2(zp1, xp, wrel2_s[7]);
                    xp = pack2(x1.x); FMA2(zp0, xp, wrel2_s[8]);  FMA2(zp1, xp, wrel2_s[9]);
                    xp = pack2(x1.y); FMA2(zp0, xp, wrel2_s[10]); FMA2(zp1, xp, wrel2_s[11]);
                    xp = pack2(x1.z); FMA2(zp0, xp, wrel2_s[12]); FMA2(zp1, xp, wrel2_s[13]);
                    xp = pack2(x1.w); FMA2(zp0, xp, wrel2_s[14]); FMA2(zp1, xp, wrel2_s[15]);
                }
                float2 zlo = unpack2(zp0);   // b0, b1
                float2 zhi = unpack2(zp1);   // b2, b3
                int spos = (((n >> 2) ^ ii) << 2) + (n & 3);
                float* zb = zb_buf + (ii * 4) * NODE_TILE + spos;
                zb[0 * NODE_TILE] = zlo.x;
                zb[1 * NODE_TILE] = zlo.y;
                zb[2 * NODE_TILE] = zhi.x;
                zb[3 * NODE_TILE] = zhi.y;
            }
            __syncthreads();   // sole barrier: A-store visible before B-read

            // ---- Phase B: acc += z_chunk @ wb_chunk ---------------------
            const __half2* wb_c = wb_h + (c * KC) * 32 + og * 2;
            #pragma unroll 8
            for (int k = 0; k < KC; k++) {
                int slot = ng ^ (k >> 2);
                float4 z4 = *(const float4*)(zb_buf + k * NODE_TILE + slot * 4);
                uint2 wh = *(const uint2*)(wb_c + k * 32);
                float2 w01 = __half22float2(*(const __half2*)&wh.x);
                float2 w23 = __half22float2(*(const __half2*)&wh.y);
                ull wp0 = pack2pair(w01.x, w01.y);
                ull wp1 = pack2pair(w23.x, w23.y);
                FMA2(acc[0][0], pack2(z4.x), wp0);
                FMA2(acc[0][1], pack2(z4.x), wp1);
                FMA2(acc[1][0], pack2(z4.y), wp0);
                FMA2(acc[1][1], pack2(z4.y), wp1);
                FMA2(acc[2][0], pack2(z4.z), wp0);
                FMA2(acc[2][1], pack2(z4.z), wp1);
                FMA2(acc[3][0], pack2(z4.w), wp0);
                FMA2(acc[3][1], pack2(z4.w), wp1);
            }
        }

        // ---- store y (fp16) --------------------------------------------
        #pragma unroll
        for (int j = 0; j < 4; j++) {
            int node = node0 + ng * 4 + j;
            if (node < n_nodes) {
                float2 a = unpack2(acc[j][0]);
                float2 b = unpack2(acc[j][1]);
                __half2 h0 = __floats2half2_rn(a.x, a.y);
                __half2 h1 = __floats2half2_rn(b.x, b.y);
                uint2 v;
                v.x = *(unsigned*)&h0;
                v.y = *(unsigned*)&h1;
                *(uint2*)(g_y + (size_t)node * D_OUT + og * 4) = v;
            }
        }
        // no tile-end barrier needed: next Phase A writes the other z buffer
    }
}

// ---------------------------------------------------------------------------
// Edge scatter: out[dst] += w_e * y_h[src]   (8 threads/edge, fp16 y)
// ---------------------------------------------------------------------------
extern "C" __global__ void rgcn_scatter(const int*   __restrict__ esrc,
                                        const int*   __restrict__ edst,
                                        const float* __restrict__ ew,
                                        float*       __restrict__ out,
                                        int n_edges)
{
    int idx = blockIdx.x * blockDim.x + threadIdx.x;
    if (idx >= n_edges * 8) return;
    int e    = idx >> 3;
    int part = idx & 7;          // 8 halves each
    int s = __ldg(esrc + e);
    int d = __ldg(edst + e);
    float w = __ldg(ew + e);
    uint4 v = ((const uint4*)(g_y + (size_t)s * D_OUT))[part];
    float2 f0 = __half22float2(*(const __half2*)&v.x);
    float2 f1 = __half22float2(*(const __half2*)&v.y);
    float2 f2 = __half22float2(*(const __half2*)&v.z);
    float2 f3 = __half22float2(*(const __half2*)&v.w);
    float* p = out + (size_t)d * D_OUT + part * 8;
    asm volatile("red.global.add.v4.f32 [%0], {%1, %2, %3, %4};"
                 :: "l"(p),     "f"(f0.x*w), "f"(f0.y*w), "f"(f1.x*w), "f"(f1.y*w) : "memory");
    asm volatile("red.global.add.v4.f32 [%0], {%1, %2, %3, %4};"
                 :: "l"(p + 4), "f"(f2.x*w), "f"(f2.y*w), "f"(f3.x*w), "f"(f3.y*w) : "memory");
}

// ---------------------------------------------------------------------------
extern "C" void kernel_launch(void* const* d_in, const int* in_sizes, int n_in,
                              void* d_out, int out_size)
{
    const float* x    = (const float*)d_in[0];
    const int*   esrc = (const int*)  d_in[1];
    const int*   edst = (const int*)  d_in[2];
    const float* ew   = (const float*)d_in[3];
    const float* wb   = (const float*)d_in[4];
    const float* wrel = (const float*)d_in[5];
    float* out = (float*)d_out;

    const int n_nodes = in_sizes[0] / (D_FEAT * N_REL);
    const int n_edges = in_sizes[1];
    const int n_tiles = (n_nodes + NODE_TILE - 1) / NODE_TILE;

    const int smem_bytes = K_DIM * 32 * sizeof(__half2)          /* 32 KB wb */
                         + 2 * KC * NODE_TILE * sizeof(float)    /* 32 KB z  */
                         + N_REL * 2 * sizeof(ull);              /* 128 B    */
    cudaFuncSetAttribute(rgcn_transform,
                         cudaFuncAttributeMaxDynamicSharedMemorySize, smem_bytes);

    cudaMemsetAsync(d_out, 0, (size_t)out_size * sizeof(float), 0);

    rgcn_transform<<<444, TBLOCK, smem_bytes>>>(x, wb, wrel, n_nodes, n_tiles);

    int total = n_edges * 8;
    int blocks = (total + TBLOCK - 1) / TBLOCK;
    rgcn_scatter<<<blocks, TBLOCK>>>(esrc, edst, ew, out, n_edges);
}